// round 1
// baseline (speedup 1.0000x reference)
#include <cuda_runtime.h>

#define NN    20000
#define BG    100
#define PERN  200
#define EE    320000
#define ETOT  340000
#define FIN   32
#define NH    10
#define C1    320
#define DOUT  128
#define NEG_SLOPE 0.2f

// ---------------- scratch (static device globals; no runtime allocation) ----
__device__ float g_XW1[NN * C1];        // layer-1 transformed feats [N, H*F]
__device__ float g_S1S[NN * NH];        // per-node per-head src attention score
__device__ float g_S1D[NN * NH];
__device__ float g_EV1[ETOT * NH];      // per-edge leaky scores, layer 1
__device__ float g_X1 [NN * C1];        // layer-1 output after elu
__device__ float g_XW2[NN * DOUT];      // layer-2 transformed feats
__device__ float g_S2S[NN];
__device__ float g_S2D[NN];
__device__ float g_EV2[ETOT];
__device__ float g_X2 [NN * DOUT];      // layer-2 output after relu
__device__ float g_POOL[BG * DOUT];     // per-graph max pooled
__device__ int   g_DEG[NN];
__device__ int   g_ROWPTR[NN + 1];
__device__ int   g_ROWCUR[NN];
__device__ int   g_EIDX[ETOT];

__device__ __forceinline__ float leakyf(float x) { return x > 0.f ? x : NEG_SLOPE * x; }
__device__ __forceinline__ float eluf(float x)   { return x > 0.f ? x : __expf(x) - 1.f; }

// ---------------- generic fp32 SGEMM: C[M,Ncols] = A[M,K] @ B[K,Ncols] -------
// BM=64, BN=128, BK=32, 256 threads, TM=8, TN=4. Optional bias+relu epilogue.
template <bool EPI>
__global__ void k_sgemm(const float* __restrict__ A, const float* __restrict__ B,
                        const float* __restrict__ bias, float* __restrict__ C,
                        int M, int Ncols, int K) {
    const int BM = 64, BN = 128, BK = 32;
    __shared__ float As[BM][BK];       // [m][k]; write kk-consecutive: conflict-free
    __shared__ float Bs[BK][BN];
    int tid = threadIdx.x;
    int ty  = tid >> 5;                 // 0..7  (warp id)
    int tx  = tid & 31;                 // lane
    int row0 = blockIdx.x * BM;
    int col0 = blockIdx.y * BN;

    float acc[8][4];
#pragma unroll
    for (int i = 0; i < 8; i++)
#pragma unroll
        for (int j = 0; j < 4; j++) acc[i][j] = 0.f;

    for (int k0 = 0; k0 < K; k0 += BK) {
#pragma unroll
        for (int i = 0; i < 8; i++) {          // 64x32 A tile, 8 elems/thread
            int e  = tid + i * 256;
            int mm = e >> 5, kk = e & 31;
            int r  = row0 + mm;
            As[mm][kk] = (r < M) ? A[(size_t)r * K + k0 + kk] : 0.f;
        }
#pragma unroll
        for (int i = 0; i < 16; i++) {         // 32x128 B tile, 16 elems/thread
            int e  = tid + i * 256;
            int kk = e >> 7, nn = e & 127;
            int c  = col0 + nn;
            Bs[kk][nn] = (c < Ncols) ? B[(size_t)(k0 + kk) * Ncols + c] : 0.f;
        }
        __syncthreads();
#pragma unroll
        for (int kk = 0; kk < BK; kk++) {
            float ra[8];
            float4 rb4 = *reinterpret_cast<const float4*>(&Bs[kk][tx * 4]);
            float rb[4] = {rb4.x, rb4.y, rb4.z, rb4.w};
#pragma unroll
            for (int i = 0; i < 8; i++) ra[i] = As[ty * 8 + i][kk];
#pragma unroll
            for (int i = 0; i < 8; i++)
#pragma unroll
                for (int j = 0; j < 4; j++)
                    acc[i][j] = fmaf(ra[i], rb[j], acc[i][j]);
        }
        __syncthreads();
    }

#pragma unroll
    for (int i = 0; i < 8; i++) {
        int r = row0 + ty * 8 + i;
        if (r >= M) continue;
#pragma unroll
        for (int j = 0; j < 4; j++) {
            int c = col0 + tx * 4 + j;
            if (c >= Ncols) continue;
            float v = acc[i][j];
            if (EPI) { v += bias[c]; v = fmaxf(v, 0.f); }
            C[(size_t)r * Ncols + c] = v;
        }
    }
}

// ---------------- per-node attention scores, layer 1 ------------------------
__global__ void k_s1(const float* __restrict__ a1s, const float* __restrict__ a1d) {
    int lane = threadIdx.x & 31;
    int n = (blockIdx.x * blockDim.x + threadIdx.x) >> 5;
    if (n >= NN) return;
    const float* x = g_XW1 + (size_t)n * C1;
#pragma unroll
    for (int h = 0; h < NH; h++) {
        float xv = x[h * 32 + lane];
        float vs = xv * a1s[h * 32 + lane];
        float vd = xv * a1d[h * 32 + lane];
#pragma unroll
        for (int o = 16; o > 0; o >>= 1) {
            vs += __shfl_down_sync(0xffffffffu, vs, o);
            vd += __shfl_down_sync(0xffffffffu, vd, o);
        }
        if (lane == 0) { g_S1S[n * NH + h] = vs; g_S1D[n * NH + h] = vd; }
    }
}

// ---------------- edge kernel layer 1: leaky scores + degree count ----------
__global__ void k_zero_deg() {
    int i = blockIdx.x * blockDim.x + threadIdx.x;
    if (i < NN) g_DEG[i] = 0;
}

__global__ void k_edge1(const int* __restrict__ esrc, const int* __restrict__ edst) {
    int e = blockIdx.x * blockDim.x + threadIdx.x;
    if (e >= ETOT) return;
    int s, d;
    if (e < EE) { s = esrc[e]; d = edst[e]; } else { s = d = e - EE; }
    const float* ps = g_S1S + (size_t)s * NH;
    const float* pd = g_S1D + (size_t)d * NH;
#pragma unroll
    for (int h = 0; h < NH; h++)
        g_EV1[(size_t)e * NH + h] = leakyf(ps[h] + pd[h]);
    atomicAdd(&g_DEG[d], 1);
}

// ---------------- single-block scan -> ROWPTR / ROWCUR ----------------------
__global__ void k_scan() {
    const int CH = 20;                         // 1024*20 >= 20000
    __shared__ int sh[1024];
    int t = threadIdx.x;
    int start = t * CH;
    int s = 0;
    for (int i = 0; i < CH; i++) {
        int idx = start + i;
        if (idx < NN) s += g_DEG[idx];
    }
    sh[t] = s;
    __syncthreads();
    for (int off = 1; off < 1024; off <<= 1) {
        int v = (t >= off) ? sh[t - off] : 0;
        __syncthreads();
        sh[t] += v;
        __syncthreads();
    }
    int run = (t > 0) ? sh[t - 1] : 0;
    for (int i = 0; i < CH; i++) {
        int idx = start + i;
        if (idx < NN) {
            g_ROWPTR[idx] = run;
            g_ROWCUR[idx] = run;
            run += g_DEG[idx];
        }
    }
    if (t == 1023) g_ROWPTR[NN] = sh[1023];
}

__global__ void k_scatter(const int* __restrict__ edst) {
    int e = blockIdx.x * blockDim.x + threadIdx.x;
    if (e >= ETOT) return;
    int d = (e < EE) ? edst[e] : e - EE;
    int pos = atomicAdd(&g_ROWCUR[d], 1);
    g_EIDX[pos] = e;
}

// ---------------- layer-1 softmax-aggregation: warp per node ----------------
// lane l owns float4 chunks {l, l+32, l+64(l<16)} of the 320-float row.
// chunk c -> head c>>3. ex for head h lives in lane h (h<10).
__global__ void k_agg1(const int* __restrict__ esrc, const float* __restrict__ b1) {
    int lane = threadIdx.x & 31;
    int n = (blockIdx.x * blockDim.x + threadIdx.x) >> 5;
    if (n >= NN) return;
    int p0 = g_ROWPTR[n], p1 = g_ROWPTR[n + 1];

    float m = -1e30f;
    for (int k = p0; k < p1; k++) {
        int eid = g_EIDX[k];
        if (lane < NH) m = fmaxf(m, g_EV1[(size_t)eid * NH + lane]);
    }

    float4 acc0 = {0,0,0,0}, acc1 = {0,0,0,0}, acc2 = {0,0,0,0};
    float denom = 0.f;
    int hsel = lane >> 3;   // 0..3

    for (int k = p0; k < p1; k++) {
        int eid = g_EIDX[k];
        float ex = 0.f;
        if (lane < NH) ex = __expf(g_EV1[(size_t)eid * NH + lane] - m);
        denom += ex;
        int s = (eid < EE) ? esrc[eid] : eid - EE;
        const float4* xr = reinterpret_cast<const float4*>(g_XW1 + (size_t)s * C1);
        float a0 = __shfl_sync(0xffffffffu, ex, hsel);
        float a1 = __shfl_sync(0xffffffffu, ex, 4 + hsel);
        float a2 = __shfl_sync(0xffffffffu, ex, 8 + hsel);  // valid for lane<16 only
        float4 v0 = xr[lane];
        float4 v1 = xr[lane + 32];
        acc0.x = fmaf(a0, v0.x, acc0.x); acc0.y = fmaf(a0, v0.y, acc0.y);
        acc0.z = fmaf(a0, v0.z, acc0.z); acc0.w = fmaf(a0, v0.w, acc0.w);
        acc1.x = fmaf(a1, v1.x, acc1.x); acc1.y = fmaf(a1, v1.y, acc1.y);
        acc1.z = fmaf(a1, v1.z, acc1.z); acc1.w = fmaf(a1, v1.w, acc1.w);
        if (lane < 16) {
            float4 v2 = xr[lane + 64];
            acc2.x = fmaf(a2, v2.x, acc2.x); acc2.y = fmaf(a2, v2.y, acc2.y);
            acc2.z = fmaf(a2, v2.z, acc2.z); acc2.w = fmaf(a2, v2.w, acc2.w);
        }
    }

    float d0 = fmaxf(__shfl_sync(0xffffffffu, denom, hsel), 1e-16f);
    float d1 = fmaxf(__shfl_sync(0xffffffffu, denom, 4 + hsel), 1e-16f);
    float d2 = fmaxf(__shfl_sync(0xffffffffu, denom, 8 + hsel), 1e-16f);

    float4* xo = reinterpret_cast<float4*>(g_X1 + (size_t)n * C1);
    const float4* bb = reinterpret_cast<const float4*>(b1);
    float4 b;
    b = bb[lane];
    float4 o;
    o.x = eluf(acc0.x / d0 + b.x); o.y = eluf(acc0.y / d0 + b.y);
    o.z = eluf(acc0.z / d0 + b.z); o.w = eluf(acc0.w / d0 + b.w);
    xo[lane] = o;
    b = bb[lane + 32];
    o.x = eluf(acc1.x / d1 + b.x); o.y = eluf(acc1.y / d1 + b.y);
    o.z = eluf(acc1.z / d1 + b.z); o.w = eluf(acc1.w / d1 + b.w);
    xo[lane + 32] = o;
    if (lane < 16) {
        b = bb[lane + 64];
        o.x = eluf(acc2.x / d2 + b.x); o.y = eluf(acc2.y / d2 + b.y);
        o.z = eluf(acc2.z / d2 + b.z); o.w = eluf(acc2.w / d2 + b.w);
        xo[lane + 64] = o;
    }
}

// ---------------- layer-2 scores -------------------------------------------
__global__ void k_s2(const float* __restrict__ a2s, const float* __restrict__ a2d) {
    int lane = threadIdx.x & 31;
    int n = (blockIdx.x * blockDim.x + threadIdx.x) >> 5;
    if (n >= NN) return;
    const float* x = g_XW2 + (size_t)n * DOUT;
    float vs = 0.f, vd = 0.f;
#pragma unroll
    for (int j = 0; j < 4; j++) {
        float xv = x[j * 32 + lane];
        vs += xv * a2s[j * 32 + lane];
        vd += xv * a2d[j * 32 + lane];
    }
#pragma unroll
    for (int o = 16; o > 0; o >>= 1) {
        vs += __shfl_down_sync(0xffffffffu, vs, o);
        vd += __shfl_down_sync(0xffffffffu, vd, o);
    }
    if (lane == 0) { g_S2S[n] = vs; g_S2D[n] = vd; }
}

__global__ void k_edge2(const int* __restrict__ esrc, const int* __restrict__ edst) {
    int e = blockIdx.x * blockDim.x + threadIdx.x;
    if (e >= ETOT) return;
    int s, d;
    if (e < EE) { s = esrc[e]; d = edst[e]; } else { s = d = e - EE; }
    g_EV2[e] = leakyf(g_S2S[s] + g_S2D[d]);
}

// ---------------- layer-2 aggregation: warp per node, 1 head ----------------
__global__ void k_agg2(const int* __restrict__ esrc, const float* __restrict__ b2) {
    int lane = threadIdx.x & 31;
    int n = (blockIdx.x * blockDim.x + threadIdx.x) >> 5;
    if (n >= NN) return;
    int p0 = g_ROWPTR[n], p1 = g_ROWPTR[n + 1];

    float m = -1e30f;
    for (int k = p0 + lane; k < p1; k += 32)
        m = fmaxf(m, g_EV2[g_EIDX[k]]);
#pragma unroll
    for (int o = 16; o > 0; o >>= 1)
        m = fmaxf(m, __shfl_xor_sync(0xffffffffu, m, o));

    float4 acc = {0,0,0,0};
    float denom = 0.f;
    for (int k = p0; k < p1; k++) {
        int eid = g_EIDX[k];
        float ex = __expf(g_EV2[eid] - m);
        denom += ex;
        int s = (eid < EE) ? esrc[eid] : eid - EE;
        float4 v = reinterpret_cast<const float4*>(g_XW2 + (size_t)s * DOUT)[lane];
        acc.x = fmaf(ex, v.x, acc.x); acc.y = fmaf(ex, v.y, acc.y);
        acc.z = fmaf(ex, v.z, acc.z); acc.w = fmaf(ex, v.w, acc.w);
    }
    float dn = fmaxf(denom, 1e-16f);
    float4 b = reinterpret_cast<const float4*>(b2)[lane];
    float4 o;
    o.x = fmaxf(acc.x / dn + b.x, 0.f);
    o.y = fmaxf(acc.y / dn + b.y, 0.f);
    o.z = fmaxf(acc.z / dn + b.z, 0.f);
    o.w = fmaxf(acc.w / dn + b.w, 0.f);
    reinterpret_cast<float4*>(g_X2 + (size_t)n * DOUT)[lane] = o;
}

// ---------------- per-graph max pool ----------------------------------------
__global__ void k_pool() {
    int g = blockIdx.x;
    int j = threadIdx.x;
    float m = -1e30f;
    const float* base = g_X2 + (size_t)g * PERN * DOUT + j;
    for (int i = 0; i < PERN; i++)
        m = fmaxf(m, base[(size_t)i * DOUT]);
    g_POOL[g * DOUT + j] = m;
}

// ============================================================================
extern "C" void kernel_launch(void* const* d_in, const int* in_sizes, int n_in,
                              void* d_out, int out_size) {
    const float* feats = (const float*)d_in[0];
    const int*   ei    = (const int*)d_in[1];
    const int*   esrc  = ei;
    const int*   edst  = ei + EE;
    const float* W1  = (const float*)d_in[4];
    const float* a1s = (const float*)d_in[5];
    const float* a1d = (const float*)d_in[6];
    const float* b1  = (const float*)d_in[7];
    const float* W2  = (const float*)d_in[8];
    const float* a2s = (const float*)d_in[9];
    const float* a2d = (const float*)d_in[10];
    const float* b2  = (const float*)d_in[11];
    const float* fcw = (const float*)d_in[12];
    const float* fcb = (const float*)d_in[13];
    float* out = (float*)d_out;

    void *pXW1, *pX1, *pXW2, *pX2, *pPOOL;
    cudaGetSymbolAddress(&pXW1, g_XW1);
    cudaGetSymbolAddress(&pX1,  g_X1);
    cudaGetSymbolAddress(&pXW2, g_XW2);
    cudaGetSymbolAddress(&pX2,  g_X2);
    cudaGetSymbolAddress(&pPOOL, g_POOL);

    const int WB = 256;                     // warp-per-node blocks
    int warpBlocks = (NN * 32 + WB - 1) / WB;

    k_zero_deg<<<(NN + 255) / 256, 256>>>();

    // GEMM1: [20000,32] @ [32,320] -> g_XW1
    dim3 g1((NN + 63) / 64, (C1 + 127) / 128);
    k_sgemm<false><<<g1, 256>>>(feats, W1, nullptr, (float*)pXW1, NN, C1, FIN);

    k_s1<<<warpBlocks, WB>>>(a1s, a1d);
    k_edge1<<<(ETOT + 255) / 256, 256>>>(esrc, edst);
    k_scan<<<1, 1024>>>();
    k_scatter<<<(ETOT + 255) / 256, 256>>>(edst);
    k_agg1<<<warpBlocks, WB>>>(esrc, b1);

    // GEMM2: [20000,320] @ [320,128] -> g_XW2
    dim3 g2((NN + 63) / 64, 1);
    k_sgemm<false><<<g2, 256>>>((const float*)pX1, W2, nullptr, (float*)pXW2, NN, DOUT, C1);

    k_s2<<<warpBlocks, WB>>>(a2s, a2d);
    k_edge2<<<(ETOT + 255) / 256, 256>>>(esrc, edst);
    k_agg2<<<warpBlocks, WB>>>(esrc, b2);

    k_pool<<<BG, 128>>>();

    // FC over all nodes: relu(X2 @ fc_w + fc_b) -> out[0 : 20000*128)
    k_sgemm<true><<<g2, 256>>>((const float*)pX2, fcw, fcb, out, NN, DOUT, DOUT);

    // FC over pooled: relu(POOL @ fc_w + fc_b) -> out[20000*128 : +100*128)
    dim3 g3((BG + 63) / 64, 1);
    k_sgemm<true><<<g3, 256>>>((const float*)pPOOL, fcw, fcb,
                               out + (size_t)NN * DOUT, BG, DOUT, DOUT);
}

// round 2
// speedup vs baseline: 1.1548x; 1.1548x over previous
#include <cuda_runtime.h>

#define NN    20000
#define BG    100
#define PERN  200
#define EE    320000
#define ETOT  340000
#define FIN   32
#define NH    10
#define C1    320
#define DOUT  128
#define NEG_SLOPE 0.2f

// ---------------- scratch (static device globals) ---------------------------
__device__ float g_XW1[NN * C1];        // layer-1 transformed feats [N, H*F]
__device__ float g_S1S[NN * NH];        // per-node per-head src attention score
__device__ float g_S1D[NN * NH];
__device__ float g_X1 [NN * C1];        // layer-1 output after elu
__device__ float g_XW2[NN * DOUT];      // layer-2 transformed feats
__device__ float g_S2S[NN];
__device__ float g_S2D[NN];
__device__ float g_X2 [NN * DOUT];      // layer-2 output after relu
__device__ float g_POOL[BG * DOUT];     // per-graph max pooled
__device__ int   g_DEG[NN];
__device__ int   g_ROWPTR[NN + 1];
__device__ int   g_ROWCUR[NN];
__device__ int   g_ESRT[ETOT];          // source node id, sorted by dst (CSR)

__device__ __forceinline__ float leakyf(float x) { return x > 0.f ? x : NEG_SLOPE * x; }
__device__ __forceinline__ float eluf(float x)   { return x > 0.f ? x : __expf(x) - 1.f; }

// ---------------- SGEMM 128x128x16, 8x8 register tile, 256 threads ----------
template <bool EPI>
__global__ __launch_bounds__(256)
void k_sgemm128(const float* __restrict__ A, const float* __restrict__ B,
                const float* __restrict__ bias, float* __restrict__ C,
                int M, int Ncols, int K) {
    __shared__ float As[16][132];   // [k][m], padded stride to cut STS conflicts
    __shared__ float Bs[16][128];   // [k][n]
    int tid  = threadIdx.x;
    int wid  = tid >> 5;
    int lane = tid & 31;
    int row0 = blockIdx.x * 128;
    int col0 = blockIdx.y * 128;
    int m0 = (wid >> 1) * 32 + (lane & 3) * 8;
    int n0 = (wid & 1) * 64 + (lane >> 2) * 8;

    float acc[8][8];
#pragma unroll
    for (int i = 0; i < 8; i++)
#pragma unroll
        for (int j = 0; j < 8; j++) acc[i][j] = 0.f;

    for (int k0 = 0; k0 < K; k0 += 16) {
#pragma unroll
        for (int i = 0; i < 2; i++) {          // A tile 128x16
            int f = tid + i * 256;
            int r = f >> 2, c4 = (f & 3) * 4;
            float4 v = {0.f, 0.f, 0.f, 0.f};
            if (row0 + r < M)
                v = *reinterpret_cast<const float4*>(A + (size_t)(row0 + r) * K + k0 + c4);
            As[c4 + 0][r] = v.x; As[c4 + 1][r] = v.y;
            As[c4 + 2][r] = v.z; As[c4 + 3][r] = v.w;
        }
#pragma unroll
        for (int i = 0; i < 2; i++) {          // B tile 16x128
            int f = tid + i * 256;
            int kk = f >> 5, c4 = (f & 31) * 4;
            float4 v = {0.f, 0.f, 0.f, 0.f};
            if (col0 + c4 < Ncols)
                v = *reinterpret_cast<const float4*>(B + (size_t)(k0 + kk) * Ncols + col0 + c4);
            *reinterpret_cast<float4*>(&Bs[kk][c4]) = v;
        }
        __syncthreads();
#pragma unroll
        for (int kk = 0; kk < 16; kk++) {
            float4 a0 = *reinterpret_cast<const float4*>(&As[kk][m0]);
            float4 a1 = *reinterpret_cast<const float4*>(&As[kk][m0 + 4]);
            float4 b0 = *reinterpret_cast<const float4*>(&Bs[kk][n0]);
            float4 b1 = *reinterpret_cast<const float4*>(&Bs[kk][n0 + 4]);
            float a[8] = {a0.x, a0.y, a0.z, a0.w, a1.x, a1.y, a1.z, a1.w};
            float b[8] = {b0.x, b0.y, b0.z, b0.w, b1.x, b1.y, b1.z, b1.w};
#pragma unroll
            for (int i = 0; i < 8; i++)
#pragma unroll
                for (int j = 0; j < 8; j++)
                    acc[i][j] = fmaf(a[i], b[j], acc[i][j]);
        }
        __syncthreads();
    }

#pragma unroll
    for (int i = 0; i < 8; i++) {
        int r = row0 + m0 + i;
        if (r >= M) continue;
#pragma unroll
        for (int jj = 0; jj < 2; jj++) {
            int c = col0 + n0 + jj * 4;
            if (c + 3 >= Ncols) continue;
            float4 o;
            o.x = acc[i][jj * 4 + 0]; o.y = acc[i][jj * 4 + 1];
            o.z = acc[i][jj * 4 + 2]; o.w = acc[i][jj * 4 + 3];
            if (EPI) {
                o.x = fmaxf(o.x + bias[c + 0], 0.f);
                o.y = fmaxf(o.y + bias[c + 1], 0.f);
                o.z = fmaxf(o.z + bias[c + 2], 0.f);
                o.w = fmaxf(o.w + bias[c + 3], 0.f);
            }
            *reinterpret_cast<float4*>(C + (size_t)r * Ncols + c) = o;
        }
    }
}

// ---------------- per-node attention scores, layer 1 ------------------------
__global__ void k_s1(const float* __restrict__ a1s, const float* __restrict__ a1d) {
    int lane = threadIdx.x & 31;
    int n = (blockIdx.x * blockDim.x + threadIdx.x) >> 5;
    if (n >= NN) return;
    const float* x = g_XW1 + (size_t)n * C1;
#pragma unroll
    for (int h = 0; h < NH; h++) {
        float xv = x[h * 32 + lane];
        float vs = xv * a1s[h * 32 + lane];
        float vd = xv * a1d[h * 32 + lane];
#pragma unroll
        for (int o = 16; o > 0; o >>= 1) {
            vs += __shfl_down_sync(0xffffffffu, vs, o);
            vd += __shfl_down_sync(0xffffffffu, vd, o);
        }
        if (lane == 0) { g_S1S[n * NH + h] = vs; g_S1D[n * NH + h] = vd; }
    }
}

// ---------------- CSR build --------------------------------------------------
__global__ void k_init_deg() {
    int i = blockIdx.x * blockDim.x + threadIdx.x;
    if (i < NN) g_DEG[i] = 1;                 // self-loop pre-counted
}

__global__ void k_count(const int* __restrict__ edst) {
    int e = blockIdx.x * blockDim.x + threadIdx.x;
    if (e < EE) atomicAdd(&g_DEG[edst[e]], 1);
}

__global__ void k_scan() {
    const int CH = 20;
    __shared__ int sh[1024];
    int t = threadIdx.x;
    int start = t * CH;
    int s = 0;
    for (int i = 0; i < CH; i++) {
        int idx = start + i;
        if (idx < NN) s += g_DEG[idx];
    }
    sh[t] = s;
    __syncthreads();
    for (int off = 1; off < 1024; off <<= 1) {
        int v = (t >= off) ? sh[t - off] : 0;
        __syncthreads();
        sh[t] += v;
        __syncthreads();
    }
    int run = (t > 0) ? sh[t - 1] : 0;
    for (int i = 0; i < CH; i++) {
        int idx = start + i;
        if (idx < NN) {
            g_ROWPTR[idx] = run;
            g_ROWCUR[idx] = run;
            run += g_DEG[idx];
        }
    }
    if (t == 1023) g_ROWPTR[NN] = sh[1023];
}

__global__ void k_scatter(const int* __restrict__ esrc, const int* __restrict__ edst) {
    int e = blockIdx.x * blockDim.x + threadIdx.x;
    if (e >= ETOT) return;
    int s, d;
    if (e < EE) { s = esrc[e]; d = edst[e]; } else { s = d = e - EE; }
    int pos = atomicAdd(&g_ROWCUR[d], 1);
    g_ESRT[pos] = s;
}

// ---------------- layer-1 softmax-aggregation: warp per node ----------------
// Scores recomputed on the fly from S1S (gather, L2-resident) + S1D (local).
__global__ void k_agg1(const float* __restrict__ b1) {
    int lane = threadIdx.x & 31;
    int n = (blockIdx.x * blockDim.x + threadIdx.x) >> 5;
    if (n >= NN) return;
    int p0 = g_ROWPTR[n], p1 = g_ROWPTR[n + 1];
    float sd = (lane < NH) ? g_S1D[n * NH + lane] : 0.f;

    float m = -1e30f;
    for (int k = p0; k < p1; k++) {
        int s = g_ESRT[k];
        if (lane < NH)
            m = fmaxf(m, leakyf(g_S1S[s * NH + lane] + sd));
    }

    float4 acc0 = {0,0,0,0}, acc1 = {0,0,0,0}, acc2 = {0,0,0,0};
    float denom = 0.f;
    int hsel = lane >> 3;

    for (int k = p0; k < p1; k++) {
        int s = g_ESRT[k];
        float ex = 0.f;
        if (lane < NH)
            ex = __expf(leakyf(g_S1S[s * NH + lane] + sd) - m);
        denom += ex;
        const float4* xr = reinterpret_cast<const float4*>(g_XW1 + (size_t)s * C1);
        float a0 = __shfl_sync(0xffffffffu, ex, hsel);
        float a1 = __shfl_sync(0xffffffffu, ex, 4 + hsel);
        float a2 = __shfl_sync(0xffffffffu, ex, 8 + hsel);
        float4 v0 = xr[lane];
        float4 v1 = xr[lane + 32];
        acc0.x = fmaf(a0, v0.x, acc0.x); acc0.y = fmaf(a0, v0.y, acc0.y);
        acc0.z = fmaf(a0, v0.z, acc0.z); acc0.w = fmaf(a0, v0.w, acc0.w);
        acc1.x = fmaf(a1, v1.x, acc1.x); acc1.y = fmaf(a1, v1.y, acc1.y);
        acc1.z = fmaf(a1, v1.z, acc1.z); acc1.w = fmaf(a1, v1.w, acc1.w);
        if (lane < 16) {
            float4 v2 = xr[lane + 64];
            acc2.x = fmaf(a2, v2.x, acc2.x); acc2.y = fmaf(a2, v2.y, acc2.y);
            acc2.z = fmaf(a2, v2.z, acc2.z); acc2.w = fmaf(a2, v2.w, acc2.w);
        }
    }

    float d0 = fmaxf(__shfl_sync(0xffffffffu, denom, hsel), 1e-16f);
    float d1 = fmaxf(__shfl_sync(0xffffffffu, denom, 4 + hsel), 1e-16f);
    float d2 = fmaxf(__shfl_sync(0xffffffffu, denom, 8 + hsel), 1e-16f);

    float4* xo = reinterpret_cast<float4*>(g_X1 + (size_t)n * C1);
    const float4* bb = reinterpret_cast<const float4*>(b1);
    float4 b, o;
    b = bb[lane];
    o.x = eluf(acc0.x / d0 + b.x); o.y = eluf(acc0.y / d0 + b.y);
    o.z = eluf(acc0.z / d0 + b.z); o.w = eluf(acc0.w / d0 + b.w);
    xo[lane] = o;
    b = bb[lane + 32];
    o.x = eluf(acc1.x / d1 + b.x); o.y = eluf(acc1.y / d1 + b.y);
    o.z = eluf(acc1.z / d1 + b.z); o.w = eluf(acc1.w / d1 + b.w);
    xo[lane + 32] = o;
    if (lane < 16) {
        b = bb[lane + 64];
        o.x = eluf(acc2.x / d2 + b.x); o.y = eluf(acc2.y / d2 + b.y);
        o.z = eluf(acc2.z / d2 + b.z); o.w = eluf(acc2.w / d2 + b.w);
        xo[lane + 64] = o;
    }
}

// ---------------- layer-2 scores ---------------------------------------------
__global__ void k_s2(const float* __restrict__ a2s, const float* __restrict__ a2d) {
    int lane = threadIdx.x & 31;
    int n = (blockIdx.x * blockDim.x + threadIdx.x) >> 5;
    if (n >= NN) return;
    const float* x = g_XW2 + (size_t)n * DOUT;
    float vs = 0.f, vd = 0.f;
#pragma unroll
    for (int j = 0; j < 4; j++) {
        float xv = x[j * 32 + lane];
        vs += xv * a2s[j * 32 + lane];
        vd += xv * a2d[j * 32 + lane];
    }
#pragma unroll
    for (int o = 16; o > 0; o >>= 1) {
        vs += __shfl_down_sync(0xffffffffu, vs, o);
        vd += __shfl_down_sync(0xffffffffu, vd, o);
    }
    if (lane == 0) { g_S2S[n] = vs; g_S2D[n] = vd; }
}

// ---------------- layer-2 aggregation: warp per node, 1 head -----------------
__global__ void k_agg2(const float* __restrict__ b2) {
    int lane = threadIdx.x & 31;
    int n = (blockIdx.x * blockDim.x + threadIdx.x) >> 5;
    if (n >= NN) return;
    int p0 = g_ROWPTR[n], p1 = g_ROWPTR[n + 1];
    float sd = g_S2D[n];

    float m = -1e30f;
    for (int k = p0 + lane; k < p1; k += 32)
        m = fmaxf(m, leakyf(g_S2S[g_ESRT[k]] + sd));
#pragma unroll
    for (int o = 16; o > 0; o >>= 1)
        m = fmaxf(m, __shfl_xor_sync(0xffffffffu, m, o));

    float4 acc = {0,0,0,0};
    float denom = 0.f;
    for (int k = p0; k < p1; k++) {
        int s = g_ESRT[k];
        float ex = __expf(leakyf(g_S2S[s] + sd) - m);
        denom += ex;
        float4 v = reinterpret_cast<const float4*>(g_XW2 + (size_t)s * DOUT)[lane];
        acc.x = fmaf(ex, v.x, acc.x); acc.y = fmaf(ex, v.y, acc.y);
        acc.z = fmaf(ex, v.z, acc.z); acc.w = fmaf(ex, v.w, acc.w);
    }
    float dn = fmaxf(denom, 1e-16f);
    float4 b = reinterpret_cast<const float4*>(b2)[lane];
    float4 o;
    o.x = fmaxf(acc.x / dn + b.x, 0.f);
    o.y = fmaxf(acc.y / dn + b.y, 0.f);
    o.z = fmaxf(acc.z / dn + b.z, 0.f);
    o.w = fmaxf(acc.w / dn + b.w, 0.f);
    reinterpret_cast<float4*>(g_X2 + (size_t)n * DOUT)[lane] = o;
}

// ---------------- per-graph max pool -----------------------------------------
__global__ void k_pool() {
    int g = blockIdx.x;
    int j = threadIdx.x;
    float m = -1e30f;
    const float* base = g_X2 + (size_t)g * PERN * DOUT + j;
    for (int i = 0; i < PERN; i++)
        m = fmaxf(m, base[(size_t)i * DOUT]);
    g_POOL[g * DOUT + j] = m;
}

// ============================================================================
extern "C" void kernel_launch(void* const* d_in, const int* in_sizes, int n_in,
                              void* d_out, int out_size) {
    const float* feats = (const float*)d_in[0];
    const int*   ei    = (const int*)d_in[1];
    const int*   esrc  = ei;
    const int*   edst  = ei + EE;
    const float* W1  = (const float*)d_in[4];
    const float* a1s = (const float*)d_in[5];
    const float* a1d = (const float*)d_in[6];
    const float* b1  = (const float*)d_in[7];
    const float* W2  = (const float*)d_in[8];
    const float* a2s = (const float*)d_in[9];
    const float* a2d = (const float*)d_in[10];
    const float* b2  = (const float*)d_in[11];
    const float* fcw = (const float*)d_in[12];
    const float* fcb = (const float*)d_in[13];
    float* out = (float*)d_out;

    void *pXW1, *pX1, *pXW2, *pX2, *pPOOL;
    cudaGetSymbolAddress(&pXW1, g_XW1);
    cudaGetSymbolAddress(&pX1,  g_X1);
    cudaGetSymbolAddress(&pXW2, g_XW2);
    cudaGetSymbolAddress(&pX2,  g_X2);
    cudaGetSymbolAddress(&pPOOL, g_POOL);

    const int WB = 256;
    int warpBlocks = (NN * 32 + WB - 1) / WB;

    // CSR build
    k_init_deg<<<(NN + 255) / 256, 256>>>();
    k_count<<<(EE + 255) / 256, 256>>>(edst);
    k_scan<<<1, 1024>>>();
    k_scatter<<<(ETOT + 255) / 256, 256>>>(esrc, edst);

    // GEMM1: [20000,32] @ [32,320]
    dim3 g1((NN + 127) / 128, (C1 + 127) / 128);
    k_sgemm128<false><<<g1, 256>>>(feats, W1, nullptr, (float*)pXW1, NN, C1, FIN);

    k_s1<<<warpBlocks, WB>>>(a1s, a1d);
    k_agg1<<<warpBlocks, WB>>>(b1);

    // GEMM2: [20000,320] @ [320,128]
    dim3 g2((NN + 127) / 128, 1);
    k_sgemm128<false><<<g2, 256>>>((const float*)pX1, W2, nullptr, (float*)pXW2, NN, DOUT, C1);

    k_s2<<<warpBlocks, WB>>>(a2s, a2d);
    k_agg2<<<warpBlocks, WB>>>(b2);

    k_pool<<<BG, 128>>>();

    // FC over all nodes -> out[0 : 20000*128)
    k_sgemm128<true><<<g2, 256>>>((const float*)pX2, fcw, fcb, out, NN, DOUT, DOUT);

    // FC over pooled -> out[20000*128 : +100*128)
    dim3 g3(1, 1);
    k_sgemm128<true><<<g3, 256>>>((const float*)pPOOL, fcw, fcb,
                                  out + (size_t)NN * DOUT, BG, DOUT, DOUT);
}

// round 3
// speedup vs baseline: 1.2268x; 1.0623x over previous
#include <cuda_runtime.h>

#define NN    20000
#define BG    100
#define PERN  200
#define EE    320000
#define ETOT  340000
#define FIN   32
#define NH    10
#define C1    320
#define C1E   340          // 320 feats + 10 s_src + 10 s_dst
#define DOUT  128
#define NEG_SLOPE 0.2f

// ---------------- scratch ----------------------------------------------------
__device__ float g_XW1E[NN * C1E];        // [feat(320) | s_src(10) | s_dst(10)]
__device__ float g_X1  [NN * C1];         // layer-1 output after elu
__device__ float g_XW2 [NN * DOUT];
__device__ float g_S2S [NN];
__device__ float g_S2D [NN];
__device__ float g_X2E [(NN + BG) * DOUT]; // node rows + BG pooled rows
__device__ float g_B1E [FIN * C1E];        // extended B for GEMM1
__device__ int   g_DEG[NN];
__device__ int   g_ROWPTR[NN + 1];
__device__ int   g_ROWCUR[NN];
__device__ int   g_ESRT[ETOT];

__device__ __forceinline__ float leakyf(float x) { return x > 0.f ? x : NEG_SLOPE * x; }
__device__ __forceinline__ float eluf(float x)   { return x > 0.f ? x : __expf(x) - 1.f; }

// ---------------- SGEMM 128x128x16, 8x8 register tile, 256 threads ----------
template <bool EPI>
__global__ __launch_bounds__(256)
void k_sgemm128(const float* __restrict__ A, const float* __restrict__ B,
                const float* __restrict__ bias, float* __restrict__ C,
                int M, int Ncols, int K) {
    __shared__ float As[16][132];
    __shared__ float Bs[16][128];
    int tid  = threadIdx.x;
    int wid  = tid >> 5;
    int lane = tid & 31;
    int row0 = blockIdx.x * 128;
    int col0 = blockIdx.y * 128;
    int m0 = (wid >> 1) * 32 + (lane & 3) * 8;
    int n0 = (wid & 1) * 64 + (lane >> 2) * 8;

    float acc[8][8];
#pragma unroll
    for (int i = 0; i < 8; i++)
#pragma unroll
        for (int j = 0; j < 8; j++) acc[i][j] = 0.f;

    for (int k0 = 0; k0 < K; k0 += 16) {
#pragma unroll
        for (int i = 0; i < 2; i++) {
            int f = tid + i * 256;
            int r = f >> 2, c4 = (f & 3) * 4;
            float4 v = {0.f, 0.f, 0.f, 0.f};
            if (row0 + r < M)
                v = *reinterpret_cast<const float4*>(A + (size_t)(row0 + r) * K + k0 + c4);
            As[c4 + 0][r] = v.x; As[c4 + 1][r] = v.y;
            As[c4 + 2][r] = v.z; As[c4 + 3][r] = v.w;
        }
#pragma unroll
        for (int i = 0; i < 2; i++) {
            int f = tid + i * 256;
            int kk = f >> 5, c4 = (f & 31) * 4;
            float4 v = {0.f, 0.f, 0.f, 0.f};
            if (col0 + c4 < Ncols)
                v = *reinterpret_cast<const float4*>(B + (size_t)(k0 + kk) * Ncols + col0 + c4);
            *reinterpret_cast<float4*>(&Bs[kk][c4]) = v;
        }
        __syncthreads();
#pragma unroll
        for (int kk = 0; kk < 16; kk++) {
            float4 a0 = *reinterpret_cast<const float4*>(&As[kk][m0]);
            float4 a1 = *reinterpret_cast<const float4*>(&As[kk][m0 + 4]);
            float4 b0 = *reinterpret_cast<const float4*>(&Bs[kk][n0]);
            float4 b1 = *reinterpret_cast<const float4*>(&Bs[kk][n0 + 4]);
            float a[8] = {a0.x, a0.y, a0.z, a0.w, a1.x, a1.y, a1.z, a1.w};
            float b[8] = {b0.x, b0.y, b0.z, b0.w, b1.x, b1.y, b1.z, b1.w};
#pragma unroll
            for (int i = 0; i < 8; i++)
#pragma unroll
                for (int j = 0; j < 8; j++)
                    acc[i][j] = fmaf(a[i], b[j], acc[i][j]);
        }
        __syncthreads();
    }

#pragma unroll
    for (int i = 0; i < 8; i++) {
        int r = row0 + m0 + i;
        if (r >= M) continue;
#pragma unroll
        for (int jj = 0; jj < 2; jj++) {
            int c = col0 + n0 + jj * 4;
            if (c + 3 >= Ncols) continue;
            float4 o;
            o.x = acc[i][jj * 4 + 0]; o.y = acc[i][jj * 4 + 1];
            o.z = acc[i][jj * 4 + 2]; o.w = acc[i][jj * 4 + 3];
            if (EPI) {
                o.x = fmaxf(o.x + bias[c + 0], 0.f);
                o.y = fmaxf(o.y + bias[c + 1], 0.f);
                o.z = fmaxf(o.z + bias[c + 2], 0.f);
                o.w = fmaxf(o.w + bias[c + 3], 0.f);
            }
            *reinterpret_cast<float4*>(C + (size_t)r * Ncols + c) = o;
        }
    }
}

// ---------------- build extended B1 [32 x 340] -------------------------------
// cols [0,320) = W1; col 320+h = W1[:,32h:32h+32] @ a1_src[h]; 330+h = a1_dst.
__global__ void k_bext1(const float* __restrict__ W1, const float* __restrict__ a1s,
                        const float* __restrict__ a1d) {
    int k = blockIdx.x;                 // 0..31
    int j = threadIdx.x;                // 0..351
    if (j >= C1E) return;
    float v;
    if (j < C1) {
        v = W1[k * C1 + j];
    } else if (j < C1 + NH) {
        int h = j - C1;
        float s = 0.f;
        for (int f = 0; f < FIN; f++)
            s += W1[k * C1 + h * FIN + f] * a1s[h * FIN + f];
        v = s;
    } else {
        int h = j - C1 - NH;
        float s = 0.f;
        for (int f = 0; f < FIN; f++)
            s += W1[k * C1 + h * FIN + f] * a1d[h * FIN + f];
        v = s;
    }
    g_B1E[k * C1E + j] = v;
}

// ---------------- CSR build ---------------------------------------------------
__global__ void k_count(const int* __restrict__ edst) {
    int e = blockIdx.x * blockDim.x + threadIdx.x;
    if (e < EE) atomicAdd(&g_DEG[edst[e]], 1);
}

__global__ void k_scan() {
    const int CH = 20;
    __shared__ int sh[1024];
    int t = threadIdx.x;
    int start = t * CH;
    int s = 0;
    for (int i = 0; i < CH; i++) {
        int idx = start + i;
        if (idx < NN) s += g_DEG[idx] + 1;     // +1 self-loop
    }
    sh[t] = s;
    __syncthreads();
    for (int off = 1; off < 1024; off <<= 1) {
        int v = (t >= off) ? sh[t - off] : 0;
        __syncthreads();
        sh[t] += v;
        __syncthreads();
    }
    int run = (t > 0) ? sh[t - 1] : 0;
    for (int i = 0; i < CH; i++) {
        int idx = start + i;
        if (idx < NN) {
            g_ROWPTR[idx] = run;
            g_ROWCUR[idx] = run;
            run += g_DEG[idx] + 1;
        }
    }
    if (t == 1023) g_ROWPTR[NN] = sh[1023];
}

__global__ void k_scatter(const int* __restrict__ esrc, const int* __restrict__ edst) {
    int e = blockIdx.x * blockDim.x + threadIdx.x;
    if (e >= ETOT) return;
    int s, d;
    if (e < EE) { s = esrc[e]; d = edst[e]; } else { s = d = e - EE; }
    int pos = atomicAdd(&g_ROWCUR[d], 1);
    g_ESRT[pos] = s;
}

// ---------------- layer-1 softmax-aggregation: warp per node ----------------
__global__ void k_agg1(const float* __restrict__ b1) {
    int lane = threadIdx.x & 31;
    int n = (blockIdx.x * blockDim.x + threadIdx.x) >> 5;
    if (n >= NN) return;
    int p0 = g_ROWPTR[n], p1 = g_ROWPTR[n + 1];
    float sd = (lane < NH) ? g_XW1E[(size_t)n * C1E + C1 + NH + lane] : 0.f;

    float m = -1e30f;
    {
        int s_next = g_ESRT[p0];
        for (int k = p0; k < p1; k++) {
            int s = s_next;
            if (k + 1 < p1) s_next = g_ESRT[k + 1];
            if (lane < NH)
                m = fmaxf(m, leakyf(g_XW1E[(size_t)s * C1E + C1 + lane] + sd));
        }
    }

    float4 acc0 = {0,0,0,0}, acc1 = {0,0,0,0}, acc2 = {0,0,0,0};
    float denom = 0.f;
    int hsel = lane >> 3;

    int s_next = g_ESRT[p0];
    for (int k = p0; k < p1; k++) {
        int s = s_next;
        if (k + 1 < p1) s_next = g_ESRT[k + 1];
        float ex = 0.f;
        const float* row = g_XW1E + (size_t)s * C1E;
        if (lane < NH)
            ex = __expf(leakyf(row[C1 + lane] + sd) - m);
        denom += ex;
        const float4* xr = reinterpret_cast<const float4*>(row);
        float a0 = __shfl_sync(0xffffffffu, ex, hsel);
        float a1 = __shfl_sync(0xffffffffu, ex, 4 + hsel);
        float a2 = __shfl_sync(0xffffffffu, ex, 8 + hsel);
        float4 v0 = xr[lane];
        float4 v1 = xr[lane + 32];
        acc0.x = fmaf(a0, v0.x, acc0.x); acc0.y = fmaf(a0, v0.y, acc0.y);
        acc0.z = fmaf(a0, v0.z, acc0.z); acc0.w = fmaf(a0, v0.w, acc0.w);
        acc1.x = fmaf(a1, v1.x, acc1.x); acc1.y = fmaf(a1, v1.y, acc1.y);
        acc1.z = fmaf(a1, v1.z, acc1.z); acc1.w = fmaf(a1, v1.w, acc1.w);
        if (lane < 16) {
            float4 v2 = xr[lane + 64];
            acc2.x = fmaf(a2, v2.x, acc2.x); acc2.y = fmaf(a2, v2.y, acc2.y);
            acc2.z = fmaf(a2, v2.z, acc2.z); acc2.w = fmaf(a2, v2.w, acc2.w);
        }
    }

    float d0 = fmaxf(__shfl_sync(0xffffffffu, denom, hsel), 1e-16f);
    float d1 = fmaxf(__shfl_sync(0xffffffffu, denom, 4 + hsel), 1e-16f);
    float d2 = fmaxf(__shfl_sync(0xffffffffu, denom, 8 + hsel), 1e-16f);

    float4* xo = reinterpret_cast<float4*>(g_X1 + (size_t)n * C1);
    const float4* bb = reinterpret_cast<const float4*>(b1);
    float4 b, o;
    b = bb[lane];
    o.x = eluf(acc0.x / d0 + b.x); o.y = eluf(acc0.y / d0 + b.y);
    o.z = eluf(acc0.z / d0 + b.z); o.w = eluf(acc0.w / d0 + b.w);
    xo[lane] = o;
    b = bb[lane + 32];
    o.x = eluf(acc1.x / d1 + b.x); o.y = eluf(acc1.y / d1 + b.y);
    o.z = eluf(acc1.z / d1 + b.z); o.w = eluf(acc1.w / d1 + b.w);
    xo[lane + 32] = o;
    if (lane < 16) {
        b = bb[lane + 64];
        o.x = eluf(acc2.x / d2 + b.x); o.y = eluf(acc2.y / d2 + b.y);
        o.z = eluf(acc2.z / d2 + b.z); o.w = eluf(acc2.w / d2 + b.w);
        xo[lane + 64] = o;
    }
}

// ---------------- layer-2 scores ---------------------------------------------
__global__ void k_s2(const float* __restrict__ a2s, const float* __restrict__ a2d) {
    int lane = threadIdx.x & 31;
    int n = (blockIdx.x * blockDim.x + threadIdx.x) >> 5;
    if (n >= NN) return;
    const float* x = g_XW2 + (size_t)n * DOUT;
    float vs = 0.f, vd = 0.f;
#pragma unroll
    for (int j = 0; j < 4; j++) {
        float xv = x[j * 32 + lane];
        vs += xv * a2s[j * 32 + lane];
        vd += xv * a2d[j * 32 + lane];
    }
#pragma unroll
    for (int o = 16; o > 0; o >>= 1) {
        vs += __shfl_down_sync(0xffffffffu, vs, o);
        vd += __shfl_down_sync(0xffffffffu, vd, o);
    }
    if (lane == 0) { g_S2S[n] = vs; g_S2D[n] = vd; }
}

// ---------------- layer-2 aggregation + fused max-pool ------------------------
__global__ void k_agg2(const float* __restrict__ b2) {
    int lane = threadIdx.x & 31;
    int n = (blockIdx.x * blockDim.x + threadIdx.x) >> 5;
    if (n >= NN) return;
    int p0 = g_ROWPTR[n], p1 = g_ROWPTR[n + 1];
    float sd = g_S2D[n];

    float m = -1e30f;
    for (int k = p0 + lane; k < p1; k += 32)
        m = fmaxf(m, leakyf(g_S2S[g_ESRT[k]] + sd));
#pragma unroll
    for (int o = 16; o > 0; o >>= 1)
        m = fmaxf(m, __shfl_xor_sync(0xffffffffu, m, o));

    float4 acc = {0,0,0,0};
    float denom = 0.f;
    int s_next = g_ESRT[p0];
    for (int k = p0; k < p1; k++) {
        int s = s_next;
        if (k + 1 < p1) s_next = g_ESRT[k + 1];
        float ex = __expf(leakyf(g_S2S[s] + sd) - m);
        denom += ex;
        float4 v = reinterpret_cast<const float4*>(g_XW2 + (size_t)s * DOUT)[lane];
        acc.x = fmaf(ex, v.x, acc.x); acc.y = fmaf(ex, v.y, acc.y);
        acc.z = fmaf(ex, v.z, acc.z); acc.w = fmaf(ex, v.w, acc.w);
    }
    float dn = fmaxf(denom, 1e-16f);
    float4 b = reinterpret_cast<const float4*>(b2)[lane];
    float4 o;
    o.x = fmaxf(acc.x / dn + b.x, 0.f);
    o.y = fmaxf(acc.y / dn + b.y, 0.f);
    o.z = fmaxf(acc.z / dn + b.z, 0.f);
    o.w = fmaxf(acc.w / dn + b.w, 0.f);
    reinterpret_cast<float4*>(g_X2E + (size_t)n * DOUT)[lane] = o;

    // fused per-graph max pool (values >= 0, int atomicMax is order-preserving)
    int grow = NN + n / PERN;
    int* pm = reinterpret_cast<int*>(g_X2E + (size_t)grow * DOUT + lane * 4);
    atomicMax(pm + 0, __float_as_int(o.x));
    atomicMax(pm + 1, __float_as_int(o.y));
    atomicMax(pm + 2, __float_as_int(o.z));
    atomicMax(pm + 3, __float_as_int(o.w));
}

// ============================================================================
extern "C" void kernel_launch(void* const* d_in, const int* in_sizes, int n_in,
                              void* d_out, int out_size) {
    const float* feats = (const float*)d_in[0];
    const int*   ei    = (const int*)d_in[1];
    const int*   esrc  = ei;
    const int*   edst  = ei + EE;
    const float* W1  = (const float*)d_in[4];
    const float* a1s = (const float*)d_in[5];
    const float* a1d = (const float*)d_in[6];
    const float* b1  = (const float*)d_in[7];
    const float* W2  = (const float*)d_in[8];
    const float* a2s = (const float*)d_in[9];
    const float* a2d = (const float*)d_in[10];
    const float* b2  = (const float*)d_in[11];
    const float* fcw = (const float*)d_in[12];
    const float* fcb = (const float*)d_in[13];
    float* out = (float*)d_out;

    void *pXW1E, *pX1, *pXW2, *pX2E, *pB1E, *pDEG;
    cudaGetSymbolAddress(&pXW1E, g_XW1E);
    cudaGetSymbolAddress(&pX1,   g_X1);
    cudaGetSymbolAddress(&pXW2,  g_XW2);
    cudaGetSymbolAddress(&pX2E,  g_X2E);
    cudaGetSymbolAddress(&pB1E,  g_B1E);
    cudaGetSymbolAddress(&pDEG,  g_DEG);

    const int WB = 256;
    int warpBlocks = (NN * 32 + WB - 1) / WB;

    // zero degree counters and pooled rows
    cudaMemsetAsync(pDEG, 0, NN * sizeof(int));
    cudaMemsetAsync((float*)pX2E + (size_t)NN * DOUT, 0, BG * DOUT * sizeof(float));

    // CSR build + extended B1
    k_count<<<(EE + 255) / 256, 256>>>(edst);
    k_bext1<<<FIN, 352>>>(W1, a1s, a1d);
    k_scan<<<1, 1024>>>();
    k_scatter<<<(ETOT + 255) / 256, 256>>>(esrc, edst);

    // GEMM1: [20000,32] @ [32,340]  (feats + fused score projections)
    dim3 g1((NN + 127) / 128, (C1E + 127) / 128);
    k_sgemm128<false><<<g1, 256>>>(feats, (const float*)pB1E, nullptr,
                                   (float*)pXW1E, NN, C1E, FIN);

    k_agg1<<<warpBlocks, WB>>>(b1);

    // GEMM2: [20000,320] @ [320,128]
    dim3 g2((NN + 127) / 128, 1);
    k_sgemm128<false><<<g2, 256>>>((const float*)pX1, W2, nullptr,
                                   (float*)pXW2, NN, DOUT, C1);

    k_s2<<<warpBlocks, WB>>>(a2s, a2d);
    k_agg2<<<warpBlocks, WB>>>(b2);

    // single FC GEMM over node rows + pooled rows -> entire output
    dim3 g3((NN + BG + 127) / 128, 1);
    k_sgemm128<true><<<g3, 256>>>((const float*)pX2E, fcw, fcb, out,
                                  NN + BG, DOUT, DOUT);
}

// round 4
// speedup vs baseline: 1.3133x; 1.0706x over previous
#include <cuda_runtime.h>

#define NN    20000
#define BG    100
#define PERN  200
#define EE    320000
#define ETOT  340000
#define FIN   32
#define NH    10
#define C1    320
#define C1E   340          // 320 feats + 10 s_src + 10 s_dst
#define DOUT  128
#define NEG_SLOPE 0.2f

// ---------------- scratch ----------------------------------------------------
__device__ float g_XW1E[NN * C1E];
__device__ float g_X1  [NN * C1];
__device__ float g_XW2 [NN * DOUT];
__device__ float g_S2S [NN];
__device__ float g_S2D [NN];
__device__ float g_X2E [(NN + BG) * DOUT];
__device__ float g_B1E [FIN * C1E];
__device__ int   g_DEG[NN];
__device__ int   g_ROWPTR[NN + 1];
__device__ int   g_ROWCUR[NN];
__device__ int   g_ESRT[ETOT];

__device__ __forceinline__ float leakyf(float x) { return x > 0.f ? x : NEG_SLOPE * x; }
__device__ __forceinline__ float eluf(float x)   { return x > 0.f ? x : __expf(x) - 1.f; }

__device__ __forceinline__ unsigned f2tf(float x) {
    unsigned r;
    asm("cvt.rna.tf32.f32 %0, %1;" : "=r"(r) : "f"(x));
    return r;
}

__device__ __forceinline__ void mma8(float* d, const unsigned* a, const unsigned* b) {
    asm volatile(
        "mma.sync.aligned.m16n8k8.row.col.f32.tf32.tf32.f32 "
        "{%0,%1,%2,%3}, {%4,%5,%6,%7}, {%8,%9}, {%0,%1,%2,%3};\n"
        : "+f"(d[0]), "+f"(d[1]), "+f"(d[2]), "+f"(d[3])
        : "r"(a[0]), "r"(a[1]), "r"(a[2]), "r"(a[3]), "r"(b[0]), "r"(b[1]));
}

// ---------------- TF32 tensor-core GEMM (3xTF32, fp32-accurate) --------------
// 128x128 block tile, BK=16, 256 threads (8 warps: 4 along M x 2 along N).
// Warp tile 32x64: 2 m16-frags x 8 n8-frags. MODE: 0 plain, 1 bias+relu.
template <int MODE>
__global__ __launch_bounds__(256)
void k_tgemm(const float* __restrict__ A, const float* __restrict__ B,
             const float* __restrict__ bias, float* __restrict__ C,
             int M, int N, int K) {
    __shared__ float As[16][136];   // [k][m]
    __shared__ float Bs[16][136];   // [k][n]
    const int tid  = threadIdx.x;
    const int lane = tid & 31;
    const int wid  = tid >> 5;
    const int qr   = lane >> 2;     // 0..7
    const int qc   = lane & 3;      // 0..3
    const int wm   = (wid & 3) * 32;
    const int wn   = (wid >> 2) * 64;
    const int row0 = blockIdx.x * 128;
    const int col0 = blockIdx.y * 128;

    float acc[2][8][4];
#pragma unroll
    for (int mf = 0; mf < 2; mf++)
#pragma unroll
        for (int nf = 0; nf < 8; nf++)
#pragma unroll
            for (int i = 0; i < 4; i++) acc[mf][nf][i] = 0.f;

    for (int k0 = 0; k0 < K; k0 += 16) {
#pragma unroll
        for (int i = 0; i < 2; i++) {              // A tile 128x16
            int f = tid + i * 256;
            int r = f >> 2, c4 = (f & 3) * 4;
            float4 v = {0.f, 0.f, 0.f, 0.f};
            if (row0 + r < M)
                v = *reinterpret_cast<const float4*>(A + (size_t)(row0 + r) * K + k0 + c4);
            As[c4 + 0][r] = v.x; As[c4 + 1][r] = v.y;
            As[c4 + 2][r] = v.z; As[c4 + 3][r] = v.w;
        }
#pragma unroll
        for (int i = 0; i < 2; i++) {              // B tile 16x128
            int f = tid + i * 256;
            int kk = f >> 5, c4 = (f & 31) * 4;
            float4 v = {0.f, 0.f, 0.f, 0.f};
            const float* src = B + (size_t)(k0 + kk) * N + col0 + c4;
            if (col0 + c4 + 3 < N) {
                v = *reinterpret_cast<const float4*>(src);
            } else {
                if (col0 + c4 + 0 < N) v.x = src[0];
                if (col0 + c4 + 1 < N) v.y = src[1];
                if (col0 + c4 + 2 < N) v.z = src[2];
                if (col0 + c4 + 3 < N) v.w = src[3];
            }
            *reinterpret_cast<float4*>(&Bs[kk][c4]) = v;
        }
        __syncthreads();

#pragma unroll
        for (int ks = 0; ks < 16; ks += 8) {
            unsigned ah[2][4], al[2][4], bh[8][2], bl[8][2];
#pragma unroll
            for (int mf = 0; mf < 2; mf++) {
                int mb = wm + mf * 16 + qr;
                float x0 = As[ks + qc][mb];
                float x1 = As[ks + qc][mb + 8];
                float x2 = As[ks + qc + 4][mb];
                float x3 = As[ks + qc + 4][mb + 8];
                ah[mf][0] = f2tf(x0); al[mf][0] = f2tf(x0 - __uint_as_float(ah[mf][0]));
                ah[mf][1] = f2tf(x1); al[mf][1] = f2tf(x1 - __uint_as_float(ah[mf][1]));
                ah[mf][2] = f2tf(x2); al[mf][2] = f2tf(x2 - __uint_as_float(ah[mf][2]));
                ah[mf][3] = f2tf(x3); al[mf][3] = f2tf(x3 - __uint_as_float(ah[mf][3]));
            }
#pragma unroll
            for (int nf = 0; nf < 8; nf++) {
                int nb = wn + nf * 8 + qr;
                float y0 = Bs[ks + qc][nb];
                float y1 = Bs[ks + qc + 4][nb];
                bh[nf][0] = f2tf(y0); bl[nf][0] = f2tf(y0 - __uint_as_float(bh[nf][0]));
                bh[nf][1] = f2tf(y1); bl[nf][1] = f2tf(y1 - __uint_as_float(bh[nf][1]));
            }
#pragma unroll
            for (int mf = 0; mf < 2; mf++)
#pragma unroll
                for (int nf = 0; nf < 8; nf++) {
                    mma8(acc[mf][nf], ah[mf], bh[nf]);
                    mma8(acc[mf][nf], al[mf], bh[nf]);
                    mma8(acc[mf][nf], ah[mf], bl[nf]);
                }
        }
        __syncthreads();
    }

#pragma unroll
    for (int mf = 0; mf < 2; mf++) {
        int r0 = row0 + wm + mf * 16 + qr;
#pragma unroll
        for (int nf = 0; nf < 8; nf++) {
            int c = col0 + wn + nf * 8 + 2 * qc;
            float2 v0 = {acc[mf][nf][0], acc[mf][nf][1]};
            float2 v1 = {acc[mf][nf][2], acc[mf][nf][3]};
            if (MODE == 1) {
                float bc0 = bias[c], bc1 = bias[c + 1];
                v0.x = fmaxf(v0.x + bc0, 0.f); v0.y = fmaxf(v0.y + bc1, 0.f);
                v1.x = fmaxf(v1.x + bc0, 0.f); v1.y = fmaxf(v1.y + bc1, 0.f);
            }
            if (r0 < M) {
                if (c + 1 < N) *reinterpret_cast<float2*>(C + (size_t)r0 * N + c) = v0;
                else if (c < N) C[(size_t)r0 * N + c] = v0.x;
            }
            if (r0 + 8 < M) {
                if (c + 1 < N) *reinterpret_cast<float2*>(C + (size_t)(r0 + 8) * N + c) = v1;
                else if (c < N) C[(size_t)(r0 + 8) * N + c] = v1.x;
            }
        }
    }
}

// ---------------- build extended B1 [32 x 340] -------------------------------
__global__ void k_bext1(const float* __restrict__ W1, const float* __restrict__ a1s,
                        const float* __restrict__ a1d) {
    int k = blockIdx.x;
    int j = threadIdx.x;
    if (j >= C1E) return;
    float v;
    if (j < C1) {
        v = W1[k * C1 + j];
    } else if (j < C1 + NH) {
        int h = j - C1;
        float s = 0.f;
        for (int f = 0; f < FIN; f++)
            s += W1[k * C1 + h * FIN + f] * a1s[h * FIN + f];
        v = s;
    } else {
        int h = j - C1 - NH;
        float s = 0.f;
        for (int f = 0; f < FIN; f++)
            s += W1[k * C1 + h * FIN + f] * a1d[h * FIN + f];
        v = s;
    }
    g_B1E[k * C1E + j] = v;
}

// ---------------- CSR build ---------------------------------------------------
__global__ void k_count(const int* __restrict__ edst) {
    int e = blockIdx.x * blockDim.x + threadIdx.x;
    if (e < EE) atomicAdd(&g_DEG[edst[e]], 1);
}

__global__ void k_scan() {
    const int CH = 20;
    __shared__ int sh[1024];
    int t = threadIdx.x;
    int start = t * CH;
    int s = 0;
    for (int i = 0; i < CH; i++) {
        int idx = start + i;
        if (idx < NN) s += g_DEG[idx] + 1;
    }
    sh[t] = s;
    __syncthreads();
    for (int off = 1; off < 1024; off <<= 1) {
        int v = (t >= off) ? sh[t - off] : 0;
        __syncthreads();
        sh[t] += v;
        __syncthreads();
    }
    int run = (t > 0) ? sh[t - 1] : 0;
    for (int i = 0; i < CH; i++) {
        int idx = start + i;
        if (idx < NN) {
            g_ROWPTR[idx] = run;
            g_ROWCUR[idx] = run;
            run += g_DEG[idx] + 1;
        }
    }
    if (t == 1023) g_ROWPTR[NN] = sh[1023];
}

__global__ void k_scatter(const int* __restrict__ esrc, const int* __restrict__ edst) {
    int e = blockIdx.x * blockDim.x + threadIdx.x;
    if (e >= ETOT) return;
    int s, d;
    if (e < EE) { s = esrc[e]; d = edst[e]; } else { s = d = e - EE; }
    int pos = atomicAdd(&g_ROWCUR[d], 1);
    g_ESRT[pos] = s;
}

// ---------------- layer-1 softmax-aggregation: warp per node ----------------
__global__ void k_agg1(const float* __restrict__ b1) {
    int lane = threadIdx.x & 31;
    int n = (blockIdx.x * blockDim.x + threadIdx.x) >> 5;
    if (n >= NN) return;
    int p0 = g_ROWPTR[n], p1 = g_ROWPTR[n + 1];
    float sd = (lane < NH) ? g_XW1E[(size_t)n * C1E + C1 + NH + lane] : 0.f;

    float m = -1e30f;
    {
        int s_next = g_ESRT[p0];
        for (int k = p0; k < p1; k++) {
            int s = s_next;
            if (k + 1 < p1) s_next = g_ESRT[k + 1];
            if (lane < NH)
                m = fmaxf(m, leakyf(g_XW1E[(size_t)s * C1E + C1 + lane] + sd));
        }
    }

    float4 acc0 = {0,0,0,0}, acc1 = {0,0,0,0}, acc2 = {0,0,0,0};
    float denom = 0.f;
    int hsel = lane >> 3;

    int s_next = g_ESRT[p0];
    for (int k = p0; k < p1; k++) {
        int s = s_next;
        if (k + 1 < p1) s_next = g_ESRT[k + 1];
        float ex = 0.f;
        const float* row = g_XW1E + (size_t)s * C1E;
        if (lane < NH)
            ex = __expf(leakyf(row[C1 + lane] + sd) - m);
        denom += ex;
        const float4* xr = reinterpret_cast<const float4*>(row);
        float a0 = __shfl_sync(0xffffffffu, ex, hsel);
        float a1 = __shfl_sync(0xffffffffu, ex, 4 + hsel);
        float a2 = __shfl_sync(0xffffffffu, ex, 8 + hsel);
        float4 v0 = xr[lane];
        float4 v1 = xr[lane + 32];
        acc0.x = fmaf(a0, v0.x, acc0.x); acc0.y = fmaf(a0, v0.y, acc0.y);
        acc0.z = fmaf(a0, v0.z, acc0.z); acc0.w = fmaf(a0, v0.w, acc0.w);
        acc1.x = fmaf(a1, v1.x, acc1.x); acc1.y = fmaf(a1, v1.y, acc1.y);
        acc1.z = fmaf(a1, v1.z, acc1.z); acc1.w = fmaf(a1, v1.w, acc1.w);
        if (lane < 16) {
            float4 v2 = xr[lane + 64];
            acc2.x = fmaf(a2, v2.x, acc2.x); acc2.y = fmaf(a2, v2.y, acc2.y);
            acc2.z = fmaf(a2, v2.z, acc2.z); acc2.w = fmaf(a2, v2.w, acc2.w);
        }
    }

    float d0 = fmaxf(__shfl_sync(0xffffffffu, denom, hsel), 1e-16f);
    float d1 = fmaxf(__shfl_sync(0xffffffffu, denom, 4 + hsel), 1e-16f);
    float d2 = fmaxf(__shfl_sync(0xffffffffu, denom, 8 + hsel), 1e-16f);

    float4* xo = reinterpret_cast<float4*>(g_X1 + (size_t)n * C1);
    const float4* bb = reinterpret_cast<const float4*>(b1);
    float4 b, o;
    b = bb[lane];
    o.x = eluf(acc0.x / d0 + b.x); o.y = eluf(acc0.y / d0 + b.y);
    o.z = eluf(acc0.z / d0 + b.z); o.w = eluf(acc0.w / d0 + b.w);
    xo[lane] = o;
    b = bb[lane + 32];
    o.x = eluf(acc1.x / d1 + b.x); o.y = eluf(acc1.y / d1 + b.y);
    o.z = eluf(acc1.z / d1 + b.z); o.w = eluf(acc1.w / d1 + b.w);
    xo[lane + 32] = o;
    if (lane < 16) {
        b = bb[lane + 64];
        o.x = eluf(acc2.x / d2 + b.x); o.y = eluf(acc2.y / d2 + b.y);
        o.z = eluf(acc2.z / d2 + b.z); o.w = eluf(acc2.w / d2 + b.w);
        xo[lane + 64] = o;
    }
}

// ---------------- layer-2 scores ---------------------------------------------
__global__ void k_s2(const float* __restrict__ a2s, const float* __restrict__ a2d) {
    int lane = threadIdx.x & 31;
    int n = (blockIdx.x * blockDim.x + threadIdx.x) >> 5;
    if (n >= NN) return;
    const float* x = g_XW2 + (size_t)n * DOUT;
    float vs = 0.f, vd = 0.f;
#pragma unroll
    for (int j = 0; j < 4; j++) {
        float xv = x[j * 32 + lane];
        vs += xv * a2s[j * 32 + lane];
        vd += xv * a2d[j * 32 + lane];
    }
#pragma unroll
    for (int o = 16; o > 0; o >>= 1) {
        vs += __shfl_down_sync(0xffffffffu, vs, o);
        vd += __shfl_down_sync(0xffffffffu, vd, o);
    }
    if (lane == 0) { g_S2S[n] = vs; g_S2D[n] = vd; }
}

// ---------------- layer-2 aggregation + fused max-pool ------------------------
__global__ void k_agg2(const float* __restrict__ b2) {
    int lane = threadIdx.x & 31;
    int n = (blockIdx.x * blockDim.x + threadIdx.x) >> 5;
    if (n >= NN) return;
    int p0 = g_ROWPTR[n], p1 = g_ROWPTR[n + 1];
    float sd = g_S2D[n];

    float m = -1e30f;
    for (int k = p0 + lane; k < p1; k += 32)
        m = fmaxf(m, leakyf(g_S2S[g_ESRT[k]] + sd));
#pragma unroll
    for (int o = 16; o > 0; o >>= 1)
        m = fmaxf(m, __shfl_xor_sync(0xffffffffu, m, o));

    float4 acc = {0,0,0,0};
    float denom = 0.f;
    int s_next = g_ESRT[p0];
    for (int k = p0; k < p1; k++) {
        int s = s_next;
        if (k + 1 < p1) s_next = g_ESRT[k + 1];
        float ex = __expf(leakyf(g_S2S[s] + sd) - m);
        denom += ex;
        float4 v = reinterpret_cast<const float4*>(g_XW2 + (size_t)s * DOUT)[lane];
        acc.x = fmaf(ex, v.x, acc.x); acc.y = fmaf(ex, v.y, acc.y);
        acc.z = fmaf(ex, v.z, acc.z); acc.w = fmaf(ex, v.w, acc.w);
    }
    float dn = fmaxf(denom, 1e-16f);
    float4 b = reinterpret_cast<const float4*>(b2)[lane];
    float4 o;
    o.x = fmaxf(acc.x / dn + b.x, 0.f);
    o.y = fmaxf(acc.y / dn + b.y, 0.f);
    o.z = fmaxf(acc.z / dn + b.z, 0.f);
    o.w = fmaxf(acc.w / dn + b.w, 0.f);
    reinterpret_cast<float4*>(g_X2E + (size_t)n * DOUT)[lane] = o;

    int grow = NN + n / PERN;
    int* pm = reinterpret_cast<int*>(g_X2E + (size_t)grow * DOUT + lane * 4);
    atomicMax(pm + 0, __float_as_int(o.x));
    atomicMax(pm + 1, __float_as_int(o.y));
    atomicMax(pm + 2, __float_as_int(o.z));
    atomicMax(pm + 3, __float_as_int(o.w));
}

// ============================================================================
extern "C" void kernel_launch(void* const* d_in, const int* in_sizes, int n_in,
                              void* d_out, int out_size) {
    const float* feats = (const float*)d_in[0];
    const int*   ei    = (const int*)d_in[1];
    const int*   esrc  = ei;
    const int*   edst  = ei + EE;
    const float* W1  = (const float*)d_in[4];
    const float* a1s = (const float*)d_in[5];
    const float* a1d = (const float*)d_in[6];
    const float* b1  = (const float*)d_in[7];
    const float* W2  = (const float*)d_in[8];
    const float* a2s = (const float*)d_in[9];
    const float* a2d = (const float*)d_in[10];
    const float* b2  = (const float*)d_in[11];
    const float* fcw = (const float*)d_in[12];
    const float* fcb = (const float*)d_in[13];
    float* out = (float*)d_out;

    void *pXW1E, *pX1, *pXW2, *pX2E, *pB1E, *pDEG;
    cudaGetSymbolAddress(&pXW1E, g_XW1E);
    cudaGetSymbolAddress(&pX1,   g_X1);
    cudaGetSymbolAddress(&pXW2,  g_XW2);
    cudaGetSymbolAddress(&pX2E,  g_X2E);
    cudaGetSymbolAddress(&pB1E,  g_B1E);
    cudaGetSymbolAddress(&pDEG,  g_DEG);

    const int WB = 256;
    int warpBlocks = (NN * 32 + WB - 1) / WB;

    cudaMemsetAsync(pDEG, 0, NN * sizeof(int));
    cudaMemsetAsync((float*)pX2E + (size_t)NN * DOUT, 0, BG * DOUT * sizeof(float));

    // CSR build + extended B1
    k_count<<<(EE + 255) / 256, 256>>>(edst);
    k_bext1<<<FIN, 352>>>(W1, a1s, a1d);
    k_scan<<<1, 1024>>>();
    k_scatter<<<(ETOT + 255) / 256, 256>>>(esrc, edst);

    // GEMM1: [20000,32] @ [32,340]  (tensor cores, 3xTF32)
    dim3 g1((NN + 127) / 128, (C1E + 127) / 128);
    k_tgemm<0><<<g1, 256>>>(feats, (const float*)pB1E, nullptr,
                            (float*)pXW1E, NN, C1E, FIN);

    k_agg1<<<warpBlocks, WB>>>(b1);

    // GEMM2: [20000,320] @ [320,128]
    dim3 g2((NN + 127) / 128, 1);
    k_tgemm<0><<<g2, 256>>>((const float*)pX1, W2, nullptr,
                            (float*)pXW2, NN, DOUT, C1);

    k_s2<<<warpBlocks, WB>>>(a2s, a2d);
    k_agg2<<<warpBlocks, WB>>>(b2);

    // single FC GEMM over node rows + pooled rows -> entire output
    dim3 g3((NN + BG + 127) / 128, 1);
    k_tgemm<1><<<g3, 256>>>((const float*)pX2E, fcw, fcb, out,
                            NN + BG, DOUT, DOUT);
}